// round 5
// baseline (speedup 1.0000x reference)
#include <cuda_runtime.h>
#include <cstdint>

// Problem constants
#define BB      64
#define TT      2048
#define NIN     64
#define NH      512
#define NOUT    64
#define FPIT    60
#define TOTIT   (FPIT + TT)

// Decomposition
#define CSIZE   8            // CTAs per cluster (H split: 64 rows each)
#define NCLUST  16           // clusters (batch split: 4 batches each)
#define PBATCH  4
#define ROWS    64           // H rows owned per CTA
#define THREADS 512
#define NWARP   16
#define JEXT    (NH + NIN)   // 576
#define JH      48           // j-slice for epilogue warps (0-7)
#define JL      24           // j-slice for head warps (8-15)

struct Smem {
    float Aext[JEXT][ROWS];     // [j][i]
    float hx[2][JEXT][4];       // extended state, double buffered
    float red[NWARP][ROWS][4];  // per-warp partials
    float Wl[8][NH];            // this rank's 8 W_lin rows
    float bs[ROWS];
    float bl[8];
    float om[NH];
    unsigned long long full[8][2]; // per-producer-rank mbarriers (count=1)
};
#define SMEM_BYTES  ((int)sizeof(Smem))
#define HXBUF_BYTES (JEXT * 4 * 4)   // 9216

__device__ __forceinline__ uint32_t smem_u32(const void* p) {
    uint32_t a;
    asm("{ .reg .u64 t; cvta.to.shared.u64 t, %1; cvt.u32.u64 %0, t; }"
        : "=r"(a) : "l"(p));
    return a;
}
__device__ __forceinline__ uint32_t mapa_u32(uint32_t addr, uint32_t rank) {
    uint32_t r;
    asm("mapa.shared::cluster.u32 %0, %1, %2;" : "=r"(r) : "r"(addr), "r"(rank));
    return r;
}
__device__ __forceinline__ unsigned long long pack2(float a) {
    unsigned long long r;
    asm("mov.b64 %0, {%1, %1};" : "=l"(r) : "r"(__float_as_uint(a)));
    return r;
}
__device__ __forceinline__ unsigned long long packab(float a, float b) {
    unsigned long long r;
    asm("mov.b64 %0, {%1, %2};" : "=l"(r) : "r"(__float_as_uint(a)), "r"(__float_as_uint(b)));
    return r;
}
__device__ __forceinline__ void unpack2(unsigned long long v, float& a, float& b) {
    uint32_t x, y;
    asm("mov.b64 {%0, %1}, %2;" : "=r"(x), "=r"(y) : "l"(v));
    a = __uint_as_float(x); b = __uint_as_float(y);
}
__device__ __forceinline__ void ffma2(unsigned long long& acc,
                                      unsigned long long a,
                                      unsigned long long b) {
    asm("fma.rn.f32x2 %0, %1, %2, %0;" : "+l"(acc) : "l"(a), "l"(b));
}
__device__ __forceinline__ float tanh_fast(float x) {
    float r;
    asm("tanh.approx.f32 %0, %1;" : "=f"(r) : "f"(x));
    return r;
}

#define MBARRIER_INIT(addr, cnt) \
    asm volatile("mbarrier.init.shared.b64 [%0], %1;" :: "r"(addr), "r"(cnt) : "memory")

#define MBAR_ARRIVE_REMOTE(addr) \
    asm volatile("mbarrier.arrive.release.cluster.shared::cluster.b64 _, [%0];" \
                 :: "r"(addr) : "memory")

#define MBAR_WAIT_CLUSTER(mbar, parity) do {                                     \
    uint32_t _m = (mbar), _p = (parity);                                         \
    asm volatile(                                                                \
        "{\n\t.reg .pred P1;\n\t"                                                \
        "WL_%=:\n\t"                                                             \
        "mbarrier.try_wait.parity.acquire.cluster.shared::cta.b64 P1, [%0], %1, 0x989680;\n\t" \
        "@P1 bra.uni WD_%=;\n\t"                                                 \
        "bra.uni WL_%=;\n\t"                                                     \
        "WD_%=:\n\t}"                                                            \
        :: "r"(_m), "r"(_p) : "memory");                                         \
} while (0)

// Fused linear head: warp (wid-8) owns output column rank*8+(wid-8).
__device__ __forceinline__ void do_head(const Smem* S, int buf, int ow, int lane,
                                        int pb0, int rank, int tt,
                                        float* __restrict__ out)
{
    unsigned long long a01 = 0ull, a23 = 0ull;
    const float* wl = &S->Wl[ow][0];
    const ulonglong2* hp = reinterpret_cast<const ulonglong2*>(&S->hx[buf][0][0]);
    #pragma unroll
    for (int k = 0; k < 16; ++k) {
        int j = k * 32 + lane;
        float w = wl[j];
        ulonglong2 hv = hp[j];
        unsigned long long ww = pack2(w);
        ffma2(a01, ww, hv.x);
        ffma2(a23, ww, hv.y);
    }
    float s0, s1, s2, s3;
    unpack2(a01, s0, s1);
    unpack2(a23, s2, s3);
    #pragma unroll
    for (int m = 16; m >= 1; m >>= 1) {
        s0 += __shfl_xor_sync(0xffffffffu, s0, m);
        s1 += __shfl_xor_sync(0xffffffffu, s1, m);
        s2 += __shfl_xor_sync(0xffffffffu, s2, m);
        s3 += __shfl_xor_sync(0xffffffffu, s3, m);
    }
    if (lane < 4) {
        float v = (lane & 1) ? ((lane & 2) ? s3 : s1)
                             : ((lane & 2) ? s2 : s0);
        out[(pb0 + lane) * (TT * NOUT) + tt * NOUT + rank * 8 + ow] =
            v + S->bl[ow];
    }
}

template<int CNT>
__device__ __forceinline__ void matvec_slice(const Smem* S, int jbase, int lane, int cur,
        unsigned long long& r0b01, unsigned long long& r0b23,
        unsigned long long& r1b01, unsigned long long& r1b23)
{
    const float2* Ap =
        reinterpret_cast<const float2*>(&S->Aext[jbase][0]) + lane;
    const ulonglong2* hp =
        reinterpret_cast<const ulonglong2*>(&S->hx[cur][jbase][0]);
    #pragma unroll 12
    for (int jj = 0; jj < CNT; ++jj) {
        float2 a = Ap[jj * 32];
        ulonglong2 hv = hp[jj];
        unsigned long long a0 = pack2(a.x);
        unsigned long long a1 = pack2(a.y);
        ffma2(r0b01, a0, hv.x);
        ffma2(r0b23, a0, hv.y);
        ffma2(r1b01, a1, hv.x);
        ffma2(r1b23, a1, hv.y);
    }
}

extern __shared__ float smem_raw[];

__global__ void __cluster_dims__(CSIZE, 1, 1) __launch_bounds__(THREADS, 1)
rnn_lyapunov_kernel(const float* __restrict__ u,
                    const float* __restrict__ W_ih,
                    const float* __restrict__ W_hh,
                    const float* __restrict__ b_ih,
                    const float* __restrict__ b_hh,
                    const float* __restrict__ omega,
                    const float* __restrict__ W_lin,
                    const float* __restrict__ b_lin,
                    float* __restrict__ out)
{
    Smem* S = reinterpret_cast<Smem*>(smem_raw);
    const int tid  = threadIdx.x;
    const int wid  = tid >> 5;
    const int lane = tid & 31;

    uint32_t rank;
    asm("mov.u32 %0, %%cluster_ctarank;" : "=r"(rank));
    const int cid = blockIdx.x >> 3;
    const int r0  = (int)rank * ROWS;
    const int pb0 = cid * PBATCH;

    // ---- one-time loads ----
    for (int j = tid; j < NH; j += THREADS) S->om[j] = omega[j];
    __syncthreads();

    for (int idx = tid; idx < ROWS * NH; idx += THREADS) {
        int i = idx >> 9;
        int j = idx & (NH - 1);
        float om = S->om[j];
        S->Aext[j][i] = W_hh[(r0 + i) * NH + j] * om * om;
    }
    for (int idx = tid; idx < ROWS * NIN; idx += THREADS) {
        int i = idx >> 6;
        int k = idx & 63;
        S->Aext[NH + k][i] = W_ih[(r0 + i) * NIN + k];
    }
    for (int idx = tid; idx < 8 * NH; idx += THREADS) {
        int o = idx >> 9;
        int j = idx & (NH - 1);
        S->Wl[o][j] = W_lin[((int)rank * 8 + o) * NH + j];
    }
    if (tid < ROWS) S->bs[tid] = b_ih[r0 + tid] + b_hh[r0 + tid];
    if (tid < 8)    S->bl[tid] = b_lin[(int)rank * 8 + tid];

    // hx[0]: h part zero, u part = u[:,0,:]
    for (int idx = tid; idx < NH * 4; idx += THREADS)
        (&S->hx[0][0][0])[idx] = 0.0f;
    if (tid < 256) {
        int p = tid >> 6, k = tid & 63;
        S->hx[0][NH + k][p] = u[(pb0 + p) * (TT * NIN) + 0 * NIN + k];
    }
    if (tid == 0) {
        #pragma unroll
        for (int r = 0; r < 8; ++r) {
            MBARRIER_INIT(smem_u32(&S->full[r][0]), 1);
            MBARRIER_INIT(smem_u32(&S->full[r][1]), 1);
        }
    }
    __syncthreads();
    asm volatile("barrier.cluster.arrive.aligned;" ::: "memory");
    asm volatile("barrier.cluster.wait.aligned;"   ::: "memory");

    // mappings
    const int i2 = tid >> 2;   // epilogue: row
    const int p2 = tid & 3;    // epilogue: batch
    const int pk = tid >> 6;   // u prefetch: batch (epilogue threads)
    const int ku = tid & 63;   // u prefetch: input idx
    const int jbase = (wid < 8) ? (JH * wid) : (8 * JH + JL * (wid - 8));

    // rank dependencies of my matvec slice (epilogue warps only read 1-2 ranks)
    const int r_lo = jbase >> 6;
    int r_hi_t = (jbase + ((wid < 8) ? JH : JL) - 1) >> 6;
    if (r_hi_t > 7) r_hi_t = 7;     // u rows (j>=512) have no barrier
    const int r_hi = r_hi_t;

    // DSMEM destinations for my (i2,p2) row: ranks p2*2 and p2*2+1
    uint32_t dstA = 0, dstB = 0;
    if (tid < 256) {
        uint32_t myrow = smem_u32(&S->hx[0][r0 + i2][0]);
        dstA = mapa_u32(myrow, (uint32_t)(p2 * 2));
        dstB = mapa_u32(myrow, (uint32_t)(p2 * 2 + 1));
    }
    // remote arrive addresses: warp 0 lanes 0-7 -> full[myrank][buf] at rank=lane
    uint32_t raA0 = 0, raA1 = 0;
    if (wid == 0 && lane < 8) {
        raA0 = mapa_u32(smem_u32(&S->full[rank][0]), (uint32_t)lane);
        raA1 = mapa_u32(smem_u32(&S->full[rank][1]), (uint32_t)lane);
    }
    // local wait addresses
    uint32_t flw[8][2];
    #pragma unroll
    for (int r = 0; r < 8; ++r) {
        flw[r][0] = smem_u32(&S->full[r][0]);
        flw[r][1] = smem_u32(&S->full[r][1]);
    }

    for (int kk = 0; kk < TOTIT; ++kk) {
        const int cur = kk & 1;
        const int nxt = cur ^ 1;
        const int t   = kk - FPIT;

        // prefetch u for step kk+1 (epilogue threads; hidden under matvec)
        float u_next = 0.0f;
        if (wid < 8) {
            int tn = kk + 1 - FPIT;
            tn = (tn < 0) ? 0 : ((tn > TT - 1) ? (TT - 1) : tn);
            u_next = u[(pb0 + pk) * (TT * NIN) + tn * NIN + ku];
        }

        // ---- waits for hx[cur] slices (skip step 0: locally initialized) ----
        if (kk > 0) {
            const uint32_t par = (uint32_t)(((kk - 1) >> 1) & 1);
            if (wid < 8) {
                MBAR_WAIT_CLUSTER(flw[r_lo][cur], par);
                if (r_hi != r_lo) MBAR_WAIT_CLUSTER(flw[r_hi][cur], par);
            } else {
                #pragma unroll
                for (int r = 0; r < 8; ++r)
                    MBAR_WAIT_CLUSTER(flw[r][cur], par);
            }
        }

        // ---- head for step t-1 on warps 8-15 (reads hx[cur], concurrent
        //      with epilogue warps' matvec) ----
        if (wid >= 8 && t >= 1)
            do_head(S, cur, wid - 8, lane, pb0, (int)rank, t - 1, out);

        // ---- matvec slice ----
        unsigned long long r0b01 = 0ull, r0b23 = 0ull, r1b01 = 0ull, r1b23 = 0ull;
        if (wid < 8)
            matvec_slice<JH>(S, jbase, lane, cur, r0b01, r0b23, r1b01, r1b23);
        else
            matvec_slice<JL>(S, jbase, lane, cur, r0b01, r0b23, r1b01, r1b23);
        {
            ulonglong2* rp = reinterpret_cast<ulonglong2*>(&S->red[wid][2 * lane][0]);
            rp[0] = make_ulonglong2(r0b01, r0b23);
            rp[1] = make_ulonglong2(r1b01, r1b23);
        }
        __syncthreads();

        // ---- epilogue on warps 0-7: reduce + tanh + transpose + exchange ----
        if (wid < 8) {
            float s = S->bs[i2];
            const float* rp = &S->red[0][i2][p2];
            #pragma unroll
            for (int q = 0; q < NWARP; ++q) s += rp[q * ROWS * 4];
            const float hn = tanh_fast(s);

            // quad transpose -> (h0..h3) packed in every lane
            float a = hn;
            float b = __shfl_xor_sync(0xffffffffu, a, 1);
            float v0 = (p2 & 1) ? b : a;
            float v1 = (p2 & 1) ? a : b;
            float c0 = __shfl_xor_sync(0xffffffffu, v0, 2);
            float c1 = __shfl_xor_sync(0xffffffffu, v1, 2);
            float h0, h1, h2, h3;
            if (p2 < 2) { h0 = v0; h1 = v1; h2 = c0; h3 = c1; }
            else        { h0 = c0; h1 = c1; h2 = v0; h3 = v1; }
            unsigned long long lo = packab(h0, h1);
            unsigned long long hi = packab(h2, h3);

            const uint32_t off = (uint32_t)nxt * HXBUF_BYTES;
            asm volatile("st.shared::cluster.b64 [%0], %1;" :: "r"(dstA + off),     "l"(lo) : "memory");
            asm volatile("st.shared::cluster.b64 [%0], %1;" :: "r"(dstA + off + 8), "l"(hi) : "memory");
            asm volatile("st.shared::cluster.b64 [%0], %1;" :: "r"(dstB + off),     "l"(lo) : "memory");
            asm volatile("st.shared::cluster.b64 [%0], %1;" :: "r"(dstB + off + 8), "l"(hi) : "memory");

            // next step's input rows (local)
            S->hx[nxt][NH + ku][pk] = u_next;

            // order all epilogue warps' stores, then announce to all ranks
            asm volatile("bar.sync 1, 256;" ::: "memory");
            if (wid == 0 && lane < 8)
                MBAR_ARRIVE_REMOTE(nxt ? raA1 : raA0);
        }
    }

    // final head: h_{TT-1} lives in hx[TOTIT&1]; wait that buffer's arrives
    {
        const int buf = TOTIT & 1;
        const uint32_t par = (uint32_t)(((TOTIT - 1) >> 1) & 1);
        if (wid >= 8) {
            #pragma unroll
            for (int r = 0; r < 8; ++r)
                MBAR_WAIT_CLUSTER(flw[r][buf], par);
            do_head(S, buf, wid - 8, lane, pb0, (int)rank, TT - 1, out);
        }
    }
}

extern "C" void kernel_launch(void* const* d_in, const int* in_sizes, int n_in,
                              void* d_out, int out_size)
{
    const float* u     = (const float*)d_in[0];
    const float* W_ih  = (const float*)d_in[1];
    const float* W_hh  = (const float*)d_in[2];
    const float* b_ih  = (const float*)d_in[3];
    const float* b_hh  = (const float*)d_in[4];
    const float* omega = (const float*)d_in[5];
    const float* W_lin = (const float*)d_in[6];
    const float* b_lin = (const float*)d_in[7];
    float* out = (float*)d_out;

    cudaFuncSetAttribute(rnn_lyapunov_kernel,
                         cudaFuncAttributeMaxDynamicSharedMemorySize,
                         SMEM_BYTES);

    rnn_lyapunov_kernel<<<NCLUST * CSIZE, THREADS, SMEM_BYTES>>>(
        u, W_ih, W_hh, b_ih, b_hh, omega, W_lin, b_lin, out);
}

// round 6
// speedup vs baseline: 1.0028x; 1.0028x over previous
#include <cuda_runtime.h>
#include <cstdint>

// Problem constants
#define BB      64
#define TT      2048
#define NIN     64
#define NH      512
#define NOUT    64
#define FPIT    60
#define TOTIT   (FPIT + TT)

// Decomposition
#define CSIZE   8            // CTAs per cluster (H split: 64 rows each)
#define NCLUST  16           // clusters (batch split: 4 batches each)
#define PBATCH  4
#define ROWS    64           // H rows owned per CTA
#define THREADS 512
#define NWARP   16
#define JEXT    (NH + NIN)   // 576
#define JH      48           // j-slice for epilogue warps (0-7)
#define JL      24           // j-slice for head warps (8-15)

struct Smem {
    float Aext[JEXT][ROWS];     // [j][i]
    float hx[2][JEXT][4];       // extended state, double buffered
    float red[NWARP][ROWS][4];  // per-warp partials
    float Wl[8][NH];            // this rank's 8 W_lin rows
    float bs[ROWS];
    float bl[8];
    float om[NH];
    unsigned long long full[8][2]; // per-producer-rank mbarriers (count=1)
};
#define SMEM_BYTES  ((int)sizeof(Smem))
#define HXBUF_BYTES (JEXT * 4 * 4)   // 9216

__device__ __forceinline__ uint32_t smem_u32(const void* p) {
    uint32_t a;
    asm("{ .reg .u64 t; cvta.to.shared.u64 t, %1; cvt.u32.u64 %0, t; }"
        : "=r"(a) : "l"(p));
    return a;
}
__device__ __forceinline__ uint32_t mapa_u32(uint32_t addr, uint32_t rank) {
    uint32_t r;
    asm("mapa.shared::cluster.u32 %0, %1, %2;" : "=r"(r) : "r"(addr), "r"(rank));
    return r;
}
__device__ __forceinline__ unsigned long long pack2(float a) {
    unsigned long long r;
    asm("mov.b64 %0, {%1, %1};" : "=l"(r) : "r"(__float_as_uint(a)));
    return r;
}
__device__ __forceinline__ unsigned long long packab(float a, float b) {
    unsigned long long r;
    asm("mov.b64 %0, {%1, %2};" : "=l"(r) : "r"(__float_as_uint(a)), "r"(__float_as_uint(b)));
    return r;
}
__device__ __forceinline__ void unpack2(unsigned long long v, float& a, float& b) {
    uint32_t x, y;
    asm("mov.b64 {%0, %1}, %2;" : "=r"(x), "=r"(y) : "l"(v));
    a = __uint_as_float(x); b = __uint_as_float(y);
}
__device__ __forceinline__ void ffma2(unsigned long long& acc,
                                      unsigned long long a,
                                      unsigned long long b) {
    asm("fma.rn.f32x2 %0, %1, %2, %0;" : "+l"(acc) : "l"(a), "l"(b));
}
__device__ __forceinline__ float tanh_fast(float x) {
    float r;
    asm("tanh.approx.f32 %0, %1;" : "=f"(r) : "f"(x));
    return r;
}

#define MBARRIER_INIT(addr, cnt) \
    asm volatile("mbarrier.init.shared.b64 [%0], %1;" :: "r"(addr), "r"(cnt) : "memory")

#define MBAR_ARRIVE_REMOTE(addr) \
    asm volatile("mbarrier.arrive.release.cluster.shared::cluster.b64 _, [%0];" \
                 :: "r"(addr) : "memory")

#define MBAR_WAIT_CLUSTER(mbar, parity) do {                                     \
    uint32_t _m = (mbar), _p = (parity);                                         \
    asm volatile(                                                                \
        "{\n\t.reg .pred P1;\n\t"                                                \
        "WL_%=:\n\t"                                                             \
        "mbarrier.try_wait.parity.acquire.cluster.shared::cta.b64 P1, [%0], %1, 0x989680;\n\t" \
        "@P1 bra.uni WD_%=;\n\t"                                                 \
        "bra.uni WL_%=;\n\t"                                                     \
        "WD_%=:\n\t}"                                                            \
        :: "r"(_m), "r"(_p) : "memory");                                         \
} while (0)

// Fused linear head: warp (wid-8) owns output column rank*8+(wid-8).
__device__ __forceinline__ void do_head(const Smem* S, int buf, int ow, int lane,
                                        int pb0, int rank, int tt,
                                        float* __restrict__ out)
{
    unsigned long long a01 = 0ull, a23 = 0ull;
    const float* wl = &S->Wl[ow][0];
    const ulonglong2* hp = reinterpret_cast<const ulonglong2*>(&S->hx[buf][0][0]);
    #pragma unroll
    for (int k = 0; k < 16; ++k) {
        int j = k * 32 + lane;
        float w = wl[j];
        ulonglong2 hv = hp[j];
        unsigned long long ww = pack2(w);
        ffma2(a01, ww, hv.x);
        ffma2(a23, ww, hv.y);
    }
    float s0, s1, s2, s3;
    unpack2(a01, s0, s1);
    unpack2(a23, s2, s3);
    #pragma unroll
    for (int m = 16; m >= 1; m >>= 1) {
        s0 += __shfl_xor_sync(0xffffffffu, s0, m);
        s1 += __shfl_xor_sync(0xffffffffu, s1, m);
        s2 += __shfl_xor_sync(0xffffffffu, s2, m);
        s3 += __shfl_xor_sync(0xffffffffu, s3, m);
    }
    if (lane < 4) {
        float v = (lane & 1) ? ((lane & 2) ? s3 : s1)
                             : ((lane & 2) ? s2 : s0);
        out[(pb0 + lane) * (TT * NOUT) + tt * NOUT + rank * 8 + ow] =
            v + S->bl[ow];
    }
}

template<int CNT>
__device__ __forceinline__ void matvec_slice(const Smem* S, int jbase, int lane, int cur,
        unsigned long long& r0b01, unsigned long long& r0b23,
        unsigned long long& r1b01, unsigned long long& r1b23)
{
    const float2* Ap =
        reinterpret_cast<const float2*>(&S->Aext[jbase][0]) + lane;
    const ulonglong2* hp =
        reinterpret_cast<const ulonglong2*>(&S->hx[cur][jbase][0]);
    #pragma unroll 12
    for (int jj = 0; jj < CNT; ++jj) {
        float2 a = Ap[jj * 32];
        ulonglong2 hv = hp[jj];
        unsigned long long a0 = pack2(a.x);
        unsigned long long a1 = pack2(a.y);
        ffma2(r0b01, a0, hv.x);
        ffma2(r0b23, a0, hv.y);
        ffma2(r1b01, a1, hv.x);
        ffma2(r1b23, a1, hv.y);
    }
}

extern __shared__ float smem_raw[];

__global__ void __cluster_dims__(CSIZE, 1, 1) __launch_bounds__(THREADS, 1)
rnn_lyapunov_kernel(const float* __restrict__ u,
                    const float* __restrict__ W_ih,
                    const float* __restrict__ W_hh,
                    const float* __restrict__ b_ih,
                    const float* __restrict__ b_hh,
                    const float* __restrict__ omega,
                    const float* __restrict__ W_lin,
                    const float* __restrict__ b_lin,
                    float* __restrict__ out)
{
    Smem* S = reinterpret_cast<Smem*>(smem_raw);
    const int tid  = threadIdx.x;
    const int wid  = tid >> 5;
    const int lane = tid & 31;

    uint32_t rank;
    asm("mov.u32 %0, %%cluster_ctarank;" : "=r"(rank));
    const int cid = blockIdx.x >> 3;
    const int r0  = (int)rank * ROWS;
    const int pb0 = cid * PBATCH;

    // ---- one-time loads ----
    for (int j = tid; j < NH; j += THREADS) S->om[j] = omega[j];
    __syncthreads();

    for (int idx = tid; idx < ROWS * NH; idx += THREADS) {
        int i = idx >> 9;
        int j = idx & (NH - 1);
        float om = S->om[j];
        S->Aext[j][i] = W_hh[(r0 + i) * NH + j] * om * om;
    }
    for (int idx = tid; idx < ROWS * NIN; idx += THREADS) {
        int i = idx >> 6;
        int k = idx & 63;
        S->Aext[NH + k][i] = W_ih[(r0 + i) * NIN + k];
    }
    for (int idx = tid; idx < 8 * NH; idx += THREADS) {
        int o = idx >> 9;
        int j = idx & (NH - 1);
        S->Wl[o][j] = W_lin[((int)rank * 8 + o) * NH + j];
    }
    if (tid < ROWS) S->bs[tid] = b_ih[r0 + tid] + b_hh[r0 + tid];
    if (tid < 8)    S->bl[tid] = b_lin[(int)rank * 8 + tid];

    // hx[0]: h part zero, u part = u[:,0,:]
    for (int idx = tid; idx < NH * 4; idx += THREADS)
        (&S->hx[0][0][0])[idx] = 0.0f;
    if (tid < 256) {
        int p = tid >> 6, k = tid & 63;
        S->hx[0][NH + k][p] = u[(pb0 + p) * (TT * NIN) + 0 * NIN + k];
    }
    if (tid == 0) {
        #pragma unroll
        for (int r = 0; r < 8; ++r) {
            MBARRIER_INIT(smem_u32(&S->full[r][0]), 1);
            MBARRIER_INIT(smem_u32(&S->full[r][1]), 1);
        }
    }
    __syncthreads();
    asm volatile("barrier.cluster.arrive.aligned;" ::: "memory");
    asm volatile("barrier.cluster.wait.aligned;"   ::: "memory");

    // mappings
    const int i2 = tid >> 2;   // epilogue: row
    const int p2 = tid & 3;    // epilogue: batch
    const int pk = tid >> 6;   // u prefetch: batch (epilogue threads)
    const int ku = tid & 63;   // u prefetch: input idx
    const int jbase = (wid < 8) ? (JH * wid) : (8 * JH + JL * (wid - 8));

    // rank dependencies of my matvec slice (epilogue warps only read 1-2 ranks)
    const int r_lo = jbase >> 6;
    int r_hi_t = (jbase + ((wid < 8) ? JH : JL) - 1) >> 6;
    if (r_hi_t > 7) r_hi_t = 7;     // u rows (j>=512) have no barrier
    const int r_hi = r_hi_t;

    // DSMEM destinations for my (i2,p2) row: ranks p2*2 and p2*2+1
    uint32_t dstA = 0, dstB = 0;
    if (tid < 256) {
        uint32_t myrow = smem_u32(&S->hx[0][r0 + i2][0]);
        dstA = mapa_u32(myrow, (uint32_t)(p2 * 2));
        dstB = mapa_u32(myrow, (uint32_t)(p2 * 2 + 1));
    }
    // remote arrive addresses: warp 0 lanes 0-7 -> full[myrank][buf] at rank=lane
    uint32_t raA0 = 0, raA1 = 0;
    if (wid == 0 && lane < 8) {
        raA0 = mapa_u32(smem_u32(&S->full[rank][0]), (uint32_t)lane);
        raA1 = mapa_u32(smem_u32(&S->full[rank][1]), (uint32_t)lane);
    }
    // local wait addresses
    uint32_t flw[8][2];
    #pragma unroll
    for (int r = 0; r < 8; ++r) {
        flw[r][0] = smem_u32(&S->full[r][0]);
        flw[r][1] = smem_u32(&S->full[r][1]);
    }

    for (int kk = 0; kk < TOTIT; ++kk) {
        const int cur = kk & 1;
        const int nxt = cur ^ 1;
        const int t   = kk - FPIT;

        // prefetch u for step kk+1 (epilogue threads; hidden under matvec)
        float u_next = 0.0f;
        if (wid < 8) {
            int tn = kk + 1 - FPIT;
            tn = (tn < 0) ? 0 : ((tn > TT - 1) ? (TT - 1) : tn);
            u_next = u[(pb0 + pk) * (TT * NIN) + tn * NIN + ku];
        }

        // ---- waits for hx[cur] slices (skip step 0: locally initialized) ----
        if (kk > 0) {
            const uint32_t par = (uint32_t)(((kk - 1) >> 1) & 1);
            if (wid < 8) {
                MBAR_WAIT_CLUSTER(flw[r_lo][cur], par);
                if (r_hi != r_lo) MBAR_WAIT_CLUSTER(flw[r_hi][cur], par);
            } else {
                #pragma unroll
                for (int r = 0; r < 8; ++r)
                    MBAR_WAIT_CLUSTER(flw[r][cur], par);
            }
        }

        // ---- head for step t-1 on warps 8-15 (reads hx[cur], concurrent
        //      with epilogue warps' matvec) ----
        if (wid >= 8 && t >= 1)
            do_head(S, cur, wid - 8, lane, pb0, (int)rank, t - 1, out);

        // ---- matvec slice ----
        unsigned long long r0b01 = 0ull, r0b23 = 0ull, r1b01 = 0ull, r1b23 = 0ull;
        if (wid < 8)
            matvec_slice<JH>(S, jbase, lane, cur, r0b01, r0b23, r1b01, r1b23);
        else
            matvec_slice<JL>(S, jbase, lane, cur, r0b01, r0b23, r1b01, r1b23);
        {
            ulonglong2* rp = reinterpret_cast<ulonglong2*>(&S->red[wid][2 * lane][0]);
            rp[0] = make_ulonglong2(r0b01, r0b23);
            rp[1] = make_ulonglong2(r1b01, r1b23);
        }
        __syncthreads();

        // ---- epilogue on warps 0-7: reduce + tanh + transpose + exchange ----
        if (wid < 8) {
            float s = S->bs[i2];
            const float* rp = &S->red[0][i2][p2];
            #pragma unroll
            for (int q = 0; q < NWARP; ++q) s += rp[q * ROWS * 4];
            const float hn = tanh_fast(s);

            // quad transpose -> (h0..h3) packed in every lane
            float a = hn;
            float b = __shfl_xor_sync(0xffffffffu, a, 1);
            float v0 = (p2 & 1) ? b : a;
            float v1 = (p2 & 1) ? a : b;
            float c0 = __shfl_xor_sync(0xffffffffu, v0, 2);
            float c1 = __shfl_xor_sync(0xffffffffu, v1, 2);
            float h0, h1, h2, h3;
            if (p2 < 2) { h0 = v0; h1 = v1; h2 = c0; h3 = c1; }
            else        { h0 = c0; h1 = c1; h2 = v0; h3 = v1; }
            unsigned long long lo = packab(h0, h1);
            unsigned long long hi = packab(h2, h3);

            const uint32_t off = (uint32_t)nxt * HXBUF_BYTES;
            asm volatile("st.shared::cluster.b64 [%0], %1;" :: "r"(dstA + off),     "l"(lo) : "memory");
            asm volatile("st.shared::cluster.b64 [%0], %1;" :: "r"(dstA + off + 8), "l"(hi) : "memory");
            asm volatile("st.shared::cluster.b64 [%0], %1;" :: "r"(dstB + off),     "l"(lo) : "memory");
            asm volatile("st.shared::cluster.b64 [%0], %1;" :: "r"(dstB + off + 8), "l"(hi) : "memory");

            // next step's input rows (local)
            S->hx[nxt][NH + ku][pk] = u_next;

            // order all epilogue warps' stores, then announce to all ranks
            asm volatile("bar.sync 1, 256;" ::: "memory");
            if (wid == 0 && lane < 8)
                MBAR_ARRIVE_REMOTE(nxt ? raA1 : raA0);
        }
    }

    // final head: h_{TT-1} lives in hx[TOTIT&1]; wait that buffer's arrives
    {
        const int buf = TOTIT & 1;
        const uint32_t par = (uint32_t)(((TOTIT - 1) >> 1) & 1);
        if (wid >= 8) {
            #pragma unroll
            for (int r = 0; r < 8; ++r)
                MBAR_WAIT_CLUSTER(flw[r][buf], par);
            do_head(S, buf, wid - 8, lane, pb0, (int)rank, TT - 1, out);
        }
    }
}

extern "C" void kernel_launch(void* const* d_in, const int* in_sizes, int n_in,
                              void* d_out, int out_size)
{
    const float* u     = (const float*)d_in[0];
    const float* W_ih  = (const float*)d_in[1];
    const float* W_hh  = (const float*)d_in[2];
    const float* b_ih  = (const float*)d_in[3];
    const float* b_hh  = (const float*)d_in[4];
    const float* omega = (const float*)d_in[5];
    const float* W_lin = (const float*)d_in[6];
    const float* b_lin = (const float*)d_in[7];
    float* out = (float*)d_out;

    cudaFuncSetAttribute(rnn_lyapunov_kernel,
                         cudaFuncAttributeMaxDynamicSharedMemorySize,
                         SMEM_BYTES);

    rnn_lyapunov_kernel<<<NCLUST * CSIZE, THREADS, SMEM_BYTES>>>(
        u, W_ih, W_hh, b_ih, b_hh, omega, W_lin, b_lin, out);
}

// round 7
// speedup vs baseline: 1.2211x; 1.2177x over previous
#include <cuda_runtime.h>
#include <cstdint>

// Problem constants
#define BB      64
#define TT      2048
#define NIN     64
#define NH      512
#define NOUT    64
#define FPIT    60
#define TOTIT   (FPIT + TT)

// Decomposition
#define CSIZE   8            // CTAs per cluster (H split: 64 rows each)
#define NCLUST  16           // clusters (batch split: 2 streams x 2 batches)
#define ROWS    64           // H rows owned per CTA
#define THREADS 512          // 2 groups x 8 warps
#define JEXT    (NH + NIN)   // 576
#define JWG     (JEXT / 8)   // 72 j per warp within a group
#define REDP    132          // padded red row (64 rows x 2 batches + 4)

struct Smem {
    float Aext[JEXT][ROWS];        // [j][i]: shared by both streams
    float hx[2][2][JEXT][2];       // [stream][buf][j][batch]
    float red[2][8][REDP];         // [stream][warp][row*2+batch] (padded)
    float Wl[8][NH];               // this rank's 8 W_lin rows
    float bs[ROWS];
    float bl[8];
    float om[NH];
    unsigned long long full[2][2]; // [stream][buf] mbarriers (count=8)
};
#define SMEM_BYTES  ((int)sizeof(Smem))
#define HXB_BYTES   (JEXT * 2 * 4)   // 4608 per buffer

__device__ __forceinline__ uint32_t smem_u32(const void* p) {
    uint32_t a;
    asm("{ .reg .u64 t; cvta.to.shared.u64 t, %1; cvt.u32.u64 %0, t; }"
        : "=r"(a) : "l"(p));
    return a;
}
__device__ __forceinline__ uint32_t mapa_u32(uint32_t addr, uint32_t rank) {
    uint32_t r;
    asm("mapa.shared::cluster.u32 %0, %1, %2;" : "=r"(r) : "r"(addr), "r"(rank));
    return r;
}
__device__ __forceinline__ unsigned long long pack2(float a) {
    unsigned long long r;
    asm("mov.b64 %0, {%1, %1};" : "=l"(r) : "r"(__float_as_uint(a)));
    return r;
}
__device__ __forceinline__ unsigned long long packab(float a, float b) {
    unsigned long long r;
    asm("mov.b64 %0, {%1, %2};" : "=l"(r) : "r"(__float_as_uint(a)), "r"(__float_as_uint(b)));
    return r;
}
__device__ __forceinline__ void unpack2(unsigned long long v, float& a, float& b) {
    uint32_t x, y;
    asm("mov.b64 {%0, %1}, %2;" : "=r"(x), "=r"(y) : "l"(v));
    a = __uint_as_float(x); b = __uint_as_float(y);
}
__device__ __forceinline__ void ffma2(unsigned long long& acc,
                                      unsigned long long a,
                                      unsigned long long b) {
    asm("fma.rn.f32x2 %0, %1, %2, %0;" : "+l"(acc) : "l"(a), "l"(b));
}
__device__ __forceinline__ float tanh_fast(float x) {
    float r;
    asm("tanh.approx.f32 %0, %1;" : "=f"(r) : "f"(x));
    return r;
}

#define MBARRIER_INIT(addr, cnt) \
    asm volatile("mbarrier.init.shared.b64 [%0], %1;" :: "r"(addr), "r"(cnt) : "memory")

#define MBAR_ARRIVE_REMOTE(addr) \
    asm volatile("mbarrier.arrive.release.cluster.shared::cluster.b64 _, [%0];" \
                 :: "r"(addr) : "memory")

#define MBAR_WAIT_CLUSTER(mbar, parity) do {                                     \
    uint32_t _m = (mbar), _p = (parity);                                         \
    asm volatile(                                                                \
        "{\n\t.reg .pred P1;\n\t"                                                \
        "WL_%=:\n\t"                                                             \
        "mbarrier.try_wait.parity.acquire.cluster.shared::cta.b64 P1, [%0], %1, 0x989680;\n\t" \
        "@P1 bra.uni WD_%=;\n\t"                                                 \
        "bra.uni WL_%=;\n\t"                                                     \
        "WD_%=:\n\t}"                                                            \
        :: "r"(_m), "r"(_p) : "memory");                                         \
} while (0)

#define GROUP_BAR(g) \
    asm volatile("bar.sync %0, 256;" :: "r"(1 + (g)) : "memory")

// Head for one stream's 2 batches: warp w of the group owns output column
// rank*8 + w. Reads hx[g][buf].
__device__ __forceinline__ void do_head(const Smem* S, int g, int buf, int w,
                                        int lane, int pb0, int rank, int tt,
                                        float* __restrict__ out)
{
    unsigned long long acc = 0ull;
    const float* wl = &S->Wl[w][0];
    const unsigned long long* hp =
        reinterpret_cast<const unsigned long long*>(&S->hx[g][buf][0][0]);
    #pragma unroll
    for (int k = 0; k < 16; ++k) {
        int j = k * 32 + lane;
        ffma2(acc, pack2(wl[j]), hp[j]);
    }
    float s0, s1;
    unpack2(acc, s0, s1);
    #pragma unroll
    for (int m = 16; m >= 1; m >>= 1) {
        s0 += __shfl_xor_sync(0xffffffffu, s0, m);
        s1 += __shfl_xor_sync(0xffffffffu, s1, m);
    }
    if (lane < 2) {
        float v = lane ? s1 : s0;
        out[(pb0 + g * 2 + lane) * (TT * NOUT) + tt * NOUT + rank * 8 + w] =
            v + S->bl[w];
    }
}

extern __shared__ float smem_raw[];

__global__ void __cluster_dims__(CSIZE, 1, 1) __launch_bounds__(THREADS, 1)
rnn_lyapunov_kernel(const float* __restrict__ u,
                    const float* __restrict__ W_ih,
                    const float* __restrict__ W_hh,
                    const float* __restrict__ b_ih,
                    const float* __restrict__ b_hh,
                    const float* __restrict__ omega,
                    const float* __restrict__ W_lin,
                    const float* __restrict__ b_lin,
                    float* __restrict__ out)
{
    Smem* S = reinterpret_cast<Smem*>(smem_raw);
    const int tid  = threadIdx.x;
    const int wid  = tid >> 5;
    const int lane = tid & 31;
    const int g    = tid >> 8;        // stream / warp-group (0 or 1)
    const int gtid = tid & 255;       // thread id within group
    const int wg   = wid & 7;         // warp id within group

    uint32_t rank;
    asm("mov.u32 %0, %%cluster_ctarank;" : "=r"(rank));
    const int cid = blockIdx.x >> 3;
    const int r0  = (int)rank * ROWS;
    const int pb0 = cid * 4;          // 4 batches per cluster (2 per stream)

    // ---- one-time loads ----
    for (int j = tid; j < NH; j += THREADS) S->om[j] = omega[j];
    __syncthreads();

    for (int idx = tid; idx < ROWS * NH; idx += THREADS) {
        int i = idx >> 9;
        int j = idx & (NH - 1);
        float om = S->om[j];
        S->Aext[j][i] = W_hh[(r0 + i) * NH + j] * om * om;
    }
    for (int idx = tid; idx < ROWS * NIN; idx += THREADS) {
        int i = idx >> 6;
        int k = idx & 63;
        S->Aext[NH + k][i] = W_ih[(r0 + i) * NIN + k];
    }
    for (int idx = tid; idx < 8 * NH; idx += THREADS) {
        int o = idx >> 9;
        int j = idx & (NH - 1);
        S->Wl[o][j] = W_lin[((int)rank * 8 + o) * NH + j];
    }
    if (tid < ROWS) S->bs[tid] = b_ih[r0 + tid] + b_hh[r0 + tid];
    if (tid < 8)    S->bl[tid] = b_lin[(int)rank * 8 + tid];

    // hx[s][0]: h part zero, u part = u[:,0,:] for that stream's 2 batches
    for (int idx = tid; idx < 2 * 2 * JEXT * 2; idx += THREADS)
        (&S->hx[0][0][0][0])[idx] = 0.0f;
    __syncthreads();
    if (tid < 256) {  // s' = tid>>7, b = (tid>>6)&1, k = tid&63
        int sp = tid >> 7, b = (tid >> 6) & 1, k = tid & 63;
        S->hx[sp][0][NH + k][b] = u[(pb0 + sp * 2 + b) * (TT * NIN) + k];
    }
    if (tid == 0) {
        MBARRIER_INIT(smem_u32(&S->full[0][0]), 8);
        MBARRIER_INIT(smem_u32(&S->full[0][1]), 8);
        MBARRIER_INIT(smem_u32(&S->full[1][0]), 8);
        MBARRIER_INIT(smem_u32(&S->full[1][1]), 8);
    }
    __syncthreads();
    asm volatile("barrier.cluster.arrive.aligned;" ::: "memory");
    asm volatile("barrier.cluster.wait.aligned;"   ::: "memory");

    // ---- per-thread precomputation ----
    const int jbase = wg * JWG;
    // epilogue mapping: row i2, quad slot q (p2 = batch half, hf = partial half)
    const int i2 = gtid >> 2;
    const int q  = gtid & 3;
    const int p2 = q >> 1;
    const int hf = q & 1;
    // u-prefetch mapping (gtid < 128)
    const int ub = gtid >> 6;
    const int uk = gtid & 63;

    // DSMEM destinations for my row i2: quad slot q serves ranks 2q and 2q+1
    const uint32_t rowaddr = smem_u32(&S->hx[g][0][r0 + i2][0]);
    const uint32_t dstA = mapa_u32(rowaddr, (uint32_t)(2 * q));
    const uint32_t dstB = mapa_u32(rowaddr, (uint32_t)(2 * q + 1));
    // remote arrive addresses (first warp of group, lanes 0-7)
    uint32_t ra0 = 0, ra1 = 0;
    if (wg == 0 && lane < 8) {
        ra0 = mapa_u32(smem_u32(&S->full[g][0]), (uint32_t)lane);
        ra1 = mapa_u32(smem_u32(&S->full[g][1]), (uint32_t)lane);
    }
    const uint32_t flw0 = smem_u32(&S->full[g][0]);
    const uint32_t flw1 = smem_u32(&S->full[g][1]);

    const float2* Abase = reinterpret_cast<const float2*>(&S->Aext[jbase][0]) + lane;

    for (int kk = 0; kk < TOTIT; ++kk) {
        const int cur = kk & 1;
        const int nxt = cur ^ 1;
        const int t   = kk - FPIT;

        // u prefetch for step kk+1 (issued before the wait; hidden)
        float u_next = 0.0f;
        if (gtid < 128) {
            int tn = kk + 1 - FPIT;
            tn = (tn < 0) ? 0 : ((tn > TT - 1) ? (TT - 1) : tn);
            u_next = u[(pb0 + g * 2 + ub) * (TT * NIN) + tn * NIN + uk];
        }

        // wait for hx[g][cur] (skip step 0: locally initialized)
        if (kk > 0)
            MBAR_WAIT_CLUSTER(cur ? flw1 : flw0, (uint32_t)(((kk - 1) >> 1) & 1));

        // ---- matvec: 2 rows x 2 batches per thread, 72 j per warp ----
        unsigned long long r0b = 0ull, r1b = 0ull;
        {
            const unsigned long long* hp =
                reinterpret_cast<const unsigned long long*>(&S->hx[g][cur][jbase][0]);
            #pragma unroll 12
            for (int jj = 0; jj < JWG; ++jj) {
                float2 a = Abase[jj * 32];
                unsigned long long hv = hp[jj];
                ffma2(r0b, pack2(a.x), hv);
                ffma2(r1b, pack2(a.y), hv);
            }
        }
        *reinterpret_cast<ulonglong2*>(&S->red[g][wg][4 * lane]) =
            make_ulonglong2(r0b, r1b);
        GROUP_BAR(g);

        // ---- epilogue: reduce 8 partials (4 + shfl pair), tanh, pack, push ----
        {
            const float* rp = &S->red[g][hf * 4][i2 * 2 + p2];
            float s = rp[0] + rp[REDP] + rp[2 * REDP] + rp[3 * REDP];
            s += __shfl_xor_sync(0xffffffffu, s, 1);   // combine partial halves
            const float hn = tanh_fast(s + S->bs[i2]);
            // other batch's value (quad bit1)
            const float hb = __shfl_xor_sync(0xffffffffu, hn, 2);
            const unsigned long long pk = p2 ? packab(hb, hn) : packab(hn, hb);

            const uint32_t off = (uint32_t)nxt * HXB_BYTES;
            asm volatile("st.shared::cluster.b64 [%0], %1;" :: "r"(dstA + off), "l"(pk) : "memory");
            asm volatile("st.shared::cluster.b64 [%0], %1;" :: "r"(dstB + off), "l"(pk) : "memory");

            if (gtid < 128)
                S->hx[g][nxt][NH + uk][ub] = u_next;
        }
        GROUP_BAR(g);

        // announce my slice to all ranks (one warp per group)
        if (wg == 0 && lane < 8)
            MBAR_ARRIVE_REMOTE(nxt ? ra1 : ra0);

        // head for step t-1 overlapped with the exchange window
        if (t >= 1)
            do_head(S, g, cur, wg, lane, pb0, (int)rank, t - 1, out);
    }

    // final head: h_{TT-1} lives in hx[g][TOTIT&1]
    {
        const int buf = TOTIT & 1;
        MBAR_WAIT_CLUSTER(buf ? flw1 : flw0, (uint32_t)(((TOTIT - 1) >> 1) & 1));
        do_head(S, g, buf, wg, lane, pb0, (int)rank, TT - 1, out);
    }
}

extern "C" void kernel_launch(void* const* d_in, const int* in_sizes, int n_in,
                              void* d_out, int out_size)
{
    const float* u     = (const float*)d_in[0];
    const float* W_ih  = (const float*)d_in[1];
    const float* W_hh  = (const float*)d_in[2];
    const float* b_ih  = (const float*)d_in[3];
    const float* b_hh  = (const float*)d_in[4];
    const float* omega = (const float*)d_in[5];
    const float* W_lin = (const float*)d_in[6];
    const float* b_lin = (const float*)d_in[7];
    float* out = (float*)d_out;

    cudaFuncSetAttribute(rnn_lyapunov_kernel,
                         cudaFuncAttributeMaxDynamicSharedMemorySize,
                         SMEM_BYTES);

    rnn_lyapunov_kernel<<<NCLUST * CSIZE, THREADS, SMEM_BYTES>>>(
        u, W_ih, W_hh, b_ih, b_hh, omega, W_lin, b_lin, out);
}

// round 8
// speedup vs baseline: 1.4949x; 1.2243x over previous
#include <cuda_runtime.h>
#include <cstdint>

// Problem constants
#define BB      64
#define TT      2048
#define NIN     64
#define NH      512
#define NOUT    64
#define FPIT    60
#define TOTIT   (FPIT + TT)

// Decomposition
#define CSIZE   8            // CTAs per cluster (H split: 64 rows each)
#define NCLUST  16           // clusters: 2 streams x 2 batches each
#define ROWS    64           // H rows owned per CTA
#define THREADS 256          // 8 warps; A lives in registers (144 f32/thread)
#define JEXT    (NH + NIN)   // 576
#define KPT     18           // j's per lane: j = lane + 32k, k<18

typedef unsigned long long ull;

struct Smem {
    float hx[2][2][JEXT][2];     // [stream][buf][j][batch]
    float Wl[8][NH];             // this rank's 8 W_lin rows
    ull   full[2][2];            // [stream][buf] mbarriers (count=8)
};
#define SMEM_BYTES  ((int)sizeof(Smem))
#define HXB_BYTES   (JEXT * 2 * 4)       // 4608 per buffer
#define HX_OFF(s, b) ((uint32_t)(((s) * 2 + (b)) * HXB_BYTES))

__device__ __forceinline__ uint32_t smem_u32(const void* p) {
    uint32_t a;
    asm("{ .reg .u64 t; cvta.to.shared.u64 t, %1; cvt.u32.u64 %0, t; }"
        : "=r"(a) : "l"(p));
    return a;
}
__device__ __forceinline__ uint32_t mapa_u32(uint32_t addr, uint32_t rank) {
    uint32_t r;
    asm("mapa.shared::cluster.u32 %0, %1, %2;" : "=r"(r) : "r"(addr), "r"(rank));
    return r;
}
__device__ __forceinline__ ull pack2(float a) {
    ull r;
    asm("mov.b64 %0, {%1, %1};" : "=l"(r) : "r"(__float_as_uint(a)));
    return r;
}
__device__ __forceinline__ ull packab(float a, float b) {
    ull r;
    asm("mov.b64 %0, {%1, %2};" : "=l"(r) : "r"(__float_as_uint(a)), "r"(__float_as_uint(b)));
    return r;
}
__device__ __forceinline__ void unpack2(ull v, float& a, float& b) {
    uint32_t x, y;
    asm("mov.b64 {%0, %1}, %2;" : "=r"(x), "=r"(y) : "l"(v));
    a = __uint_as_float(x); b = __uint_as_float(y);
}
__device__ __forceinline__ void ffma2(ull& acc, ull a, ull b) {
    asm("fma.rn.f32x2 %0, %1, %2, %0;" : "+l"(acc) : "l"(a), "l"(b));
}
__device__ __forceinline__ ull addf2(ull a, ull b) {
    ull r;
    asm("add.rn.f32x2 %0, %1, %2;" : "=l"(r) : "l"(a), "l"(b));
    return r;
}
__device__ __forceinline__ float tanh_fast(float x) {
    float r;
    asm("tanh.approx.f32 %0, %1;" : "=f"(r) : "f"(x));
    return r;
}

#define MBARRIER_INIT(addr, cnt) \
    asm volatile("mbarrier.init.shared.b64 [%0], %1;" :: "r"(addr), "r"(cnt) : "memory")

#define MBAR_ARRIVE_REMOTE(addr) \
    asm volatile("mbarrier.arrive.release.cluster.shared::cluster.b64 _, [%0];" \
                 :: "r"(addr) : "memory")

#define MBAR_WAIT_CLUSTER(mbar, parity) do {                                     \
    uint32_t _m = (mbar), _p = (parity);                                         \
    asm volatile(                                                                \
        "{\n\t.reg .pred P1;\n\t"                                                \
        "WL_%=:\n\t"                                                             \
        "mbarrier.try_wait.parity.acquire.cluster.shared::cta.b64 P1, [%0], %1, 0x989680;\n\t" \
        "@P1 bra.uni WD_%=;\n\t"                                                 \
        "bra.uni WL_%=;\n\t"                                                     \
        "WD_%=:\n\t}"                                                            \
        :: "r"(_m), "r"(_p) : "memory");                                         \
} while (0)

// Head for stream s (2 batches): warp w owns output column rank*8 + w.
__device__ __forceinline__ void do_head(const Smem* S, const ull* hp, int w,
                                        int lane, int pb0, int s, int rank,
                                        float blr, int tt, float* __restrict__ out)
{
    ull acc = 0ull;
    const float* wl = &S->Wl[w][0];
    #pragma unroll
    for (int k = 0; k < 16; ++k) {
        int j = k * 32 + lane;
        ffma2(acc, pack2(wl[j]), hp[j]);
    }
    #pragma unroll
    for (int m = 16; m >= 1; m >>= 1)
        acc = addf2(acc, __shfl_xor_sync(0xffffffffu, acc, m));
    if (lane < 2) {
        float s0, s1;
        unpack2(acc, s0, s1);
        float v = lane ? s1 : s0;
        out[(pb0 + s * 2 + lane) * (TT * NOUT) + tt * NOUT + rank * 8 + w] = v + blr;
    }
}

extern __shared__ float smem_raw[];

__global__ void __cluster_dims__(CSIZE, 1, 1) __launch_bounds__(THREADS, 1)
rnn_lyapunov_kernel(const float* __restrict__ u,
                    const float* __restrict__ W_ih,
                    const float* __restrict__ W_hh,
                    const float* __restrict__ b_ih,
                    const float* __restrict__ b_hh,
                    const float* __restrict__ omega,
                    const float* __restrict__ W_lin,
                    const float* __restrict__ b_lin,
                    float* __restrict__ out)
{
    Smem* S = reinterpret_cast<Smem*>(smem_raw);
    const int tid  = threadIdx.x;
    const int w    = tid >> 5;
    const int lane = tid & 31;

    uint32_t rank;
    asm("mov.u32 %0, %%cluster_ctarank;" : "=r"(rank));
    const int cid = blockIdx.x >> 3;
    const int r0  = (int)rank * ROWS;
    const int pb0 = cid * 4;

    // ---- A into registers: 8 rows x 18 j per thread ----
    float Areg[8 * KPT];
    {
        const int rg0 = r0 + w * 8;
        #pragma unroll
        for (int r = 0; r < 8; ++r) {
            const int rg = rg0 + r;
            #pragma unroll
            for (int k = 0; k < 16; ++k) {
                int j = lane + 32 * k;
                float om = omega[j];
                Areg[r * KPT + k] = W_hh[rg * NH + j] * om * om;
            }
            Areg[r * KPT + 16] = W_ih[rg * NIN + lane];
            Areg[r * KPT + 17] = W_ih[rg * NIN + 32 + lane];
        }
    }

    // ---- SMEM one-time loads ----
    for (int idx = tid; idx < 8 * NH; idx += THREADS) {
        int o = idx >> 9;
        int j = idx & (NH - 1);
        S->Wl[o][j] = W_lin[((int)rank * 8 + o) * NH + j];
    }
    // hx[s][0]: h zero, u rows = u[:,0,:]
    for (int idx = tid; idx < 2 * 2 * JEXT * 2; idx += THREADS)
        (&S->hx[0][0][0][0])[idx] = 0.0f;
    __syncthreads();
    if (tid < 128) {
        int b = tid & 1, ju = tid >> 1;
        S->hx[0][0][NH + ju][b] = u[(pb0 + 0 + b) * (TT * NIN) + ju];
        S->hx[1][0][NH + ju][b] = u[(pb0 + 2 + b) * (TT * NIN) + ju];
    }
    if (tid == 0) {
        MBARRIER_INIT(smem_u32(&S->full[0][0]), 8);
        MBARRIER_INIT(smem_u32(&S->full[0][1]), 8);
        MBARRIER_INIT(smem_u32(&S->full[1][0]), 8);
        MBARRIER_INIT(smem_u32(&S->full[1][1]), 8);
    }
    __syncthreads();
    asm volatile("barrier.cluster.arrive.aligned;" ::: "memory");
    asm volatile("barrier.cluster.wait.aligned;"   ::: "memory");

    // ---- per-thread precomputation ----
    // reduce result mapping: lane holds local row rl, serves 2 ranks
    const int rl    = (lane >> 2) & 7;        // 0..7
    const int i_loc = w * 8 + rl;             // row within CTA slice
    const float bias_r = b_ih[r0 + i_loc] + b_hh[r0 + i_loc];
    const float blr    = b_lin[(int)rank * 8 + w];
    const uint32_t rowbase = smem_u32(&S->hx[0][0][r0 + i_loc][0]);
    const uint32_t dst0 = mapa_u32(rowbase, (uint32_t)(2 * (lane & 3)));
    const uint32_t dst1 = mapa_u32(rowbase, (uint32_t)(2 * (lane & 3) + 1));
    // remote arrive addresses: warp0 lanes 0-7, per stream/buffer
    uint32_t ra[2][2] = {{0, 0}, {0, 0}};
    if (w == 0 && lane < 8) {
        ra[0][0] = mapa_u32(smem_u32(&S->full[0][0]), (uint32_t)lane);
        ra[0][1] = mapa_u32(smem_u32(&S->full[0][1]), (uint32_t)lane);
        ra[1][0] = mapa_u32(smem_u32(&S->full[1][0]), (uint32_t)lane);
        ra[1][1] = mapa_u32(smem_u32(&S->full[1][1]), (uint32_t)lane);
    }
    uint32_t flw[2][2];
    flw[0][0] = smem_u32(&S->full[0][0]);
    flw[0][1] = smem_u32(&S->full[0][1]);
    flw[1][0] = smem_u32(&S->full[1][0]);
    flw[1][1] = smem_u32(&S->full[1][1]);

    const int ub = tid & 1;      // u prefetch: batch (tid<128)
    const int ju = tid >> 1;     // u prefetch: input idx

    for (int kk = 0; kk < TOTIT; ++kk) {
        const int cur = kk & 1;
        const int nxt = cur ^ 1;
        const int t   = kk - FPIT;

        #pragma unroll
        for (int s = 0; s < 2; ++s) {
            // u prefetch for step kk+1 (before the wait; hidden)
            float u_next = 0.0f;
            if (tid < 128) {
                int tn = kk + 1 - FPIT;
                tn = (tn < 0) ? 0 : ((tn > TT - 1) ? (TT - 1) : tn);
                u_next = u[(pb0 + s * 2 + ub) * (TT * NIN) + tn * NIN + ju];
            }

            // wait for hx[s][cur] (skip step 0: locally initialized)
            if (kk > 0)
                MBAR_WAIT_CLUSTER(flw[s][cur], (uint32_t)(((kk - 1) >> 1) & 1));

            const ull* hp = reinterpret_cast<const ull*>(&S->hx[s][cur][0][0]);

            // ---- matvec from registers: d[r] = sum_j A[r][j]*h[j][0..1] ----
            ull d[8] = {0ull, 0ull, 0ull, 0ull, 0ull, 0ull, 0ull, 0ull};
            #pragma unroll
            for (int k = 0; k < KPT; ++k) {
                ull hv = hp[lane + 32 * k];
                #pragma unroll
                for (int r = 0; r < 8; ++r)
                    ffma2(d[r], pack2(Areg[r * KPT + k]), hv);
            }

            // ---- distribute-reduce within the warp ----
            // L1 (xor 16): keep 4 accs
            {
                const bool sel = (lane & 16) != 0;
                #pragma unroll
                for (int i = 0; i < 4; ++i) {
                    ull snd = sel ? d[i] : d[i + 4];
                    ull rcv = __shfl_xor_sync(0xffffffffu, snd, 16);
                    d[i] = addf2(sel ? d[i + 4] : d[i], rcv);
                }
            }
            // L2 (xor 8): keep 2
            {
                const bool sel = (lane & 8) != 0;
                #pragma unroll
                for (int i = 0; i < 2; ++i) {
                    ull snd = sel ? d[i] : d[i + 2];
                    ull rcv = __shfl_xor_sync(0xffffffffu, snd, 8);
                    d[i] = addf2(sel ? d[i + 2] : d[i], rcv);
                }
            }
            // L3 (xor 4): keep 1  -> row rl = (lane>>2)&7
            ull dd;
            {
                const bool sel = (lane & 4) != 0;
                ull snd = sel ? d[0] : d[1];
                ull rcv = __shfl_xor_sync(0xffffffffu, snd, 4);
                dd = addf2(sel ? d[1] : d[0], rcv);
            }
            // L4/L5: full butterfly over remaining lane bits (4 copies)
            dd = addf2(dd, __shfl_xor_sync(0xffffffffu, dd, 2));
            dd = addf2(dd, __shfl_xor_sync(0xffffffffu, dd, 1));

            // ---- bias + tanh + DSMEM push (each lane: 1 row -> 2 ranks) ----
            {
                float s0, s1;
                unpack2(dd, s0, s1);
                const float h0 = tanh_fast(s0 + bias_r);
                const float h1 = tanh_fast(s1 + bias_r);
                const ull pk = packab(h0, h1);
                const uint32_t off = HX_OFF(s, nxt);
                asm volatile("st.shared::cluster.b64 [%0], %1;" :: "r"(dst0 + off), "l"(pk) : "memory");
                asm volatile("st.shared::cluster.b64 [%0], %1;" :: "r"(dst1 + off), "l"(pk) : "memory");
            }
            // next step's input rows (local)
            if (tid < 128)
                S->hx[s][nxt][NH + ju][ub] = u_next;

            __syncthreads();
            if (w == 0 && lane < 8)
                MBAR_ARRIVE_REMOTE(ra[s][nxt]);

            // head for step t-1 (reads hx[s][cur]; fills the exchange window)
            if (t >= 1)
                do_head(S, hp, w, lane, pb0, s, (int)rank, blr, t - 1, out);
        }
    }

    // final heads: h_{TT-1} lives in hx[s][TOTIT&1]
    {
        const int buf = TOTIT & 1;
        const uint32_t par = (uint32_t)(((TOTIT - 1) >> 1) & 1);
        #pragma unroll
        for (int s = 0; s < 2; ++s) {
            MBAR_WAIT_CLUSTER(flw[s][buf], par);
            const ull* hp = reinterpret_cast<const ull*>(&S->hx[s][buf][0][0]);
            do_head(S, hp, w, lane, pb0, s, (int)rank, blr, TT - 1, out);
        }
    }
}

extern "C" void kernel_launch(void* const* d_in, const int* in_sizes, int n_in,
                              void* d_out, int out_size)
{
    const float* u     = (const float*)d_in[0];
    const float* W_ih  = (const float*)d_in[1];
    const float* W_hh  = (const float*)d_in[2];
    const float* b_ih  = (const float*)d_in[3];
    const float* b_hh  = (const float*)d_in[4];
    const float* omega = (const float*)d_in[5];
    const float* W_lin = (const float*)d_in[6];
    const float* b_lin = (const float*)d_in[7];
    float* out = (float*)d_out;

    cudaFuncSetAttribute(rnn_lyapunov_kernel,
                         cudaFuncAttributeMaxDynamicSharedMemorySize,
                         SMEM_BYTES);

    rnn_lyapunov_kernel<<<NCLUST * CSIZE, THREADS, SMEM_BYTES>>>(
        u, W_ih, W_hh, b_ih, b_hh, omega, W_lin, b_lin, out);
}